// round 12
// baseline (speedup 1.0000x reference)
#include <cuda_runtime.h>
#include <cuda_fp16.h>
#include <math.h>
#include <stdint.h>

// Problem constants
#define B_    4
#define CIN   16
#define T_    31
#define H_    128
#define W_    128
#define HID   16
#define HW    (H_*W_)

// Arch-specific feature gate: tcgen05 PTX only assembles for sm_103a/f targets.
#if (defined(__CUDA_ARCH_SPECIFIC__) && (__CUDA_ARCH_SPECIFIC__ >= 1000)) || \
    (defined(__CUDA_ARCH_FAMILY_SPECIFIC__) && (__CUDA_ARCH_FAMILY_SPECIFIC__ >= 1000))
#define TC_PATH 1
#else
#define TC_PATH 0
#endif

// ===========================================================================
// Persistent fused conv + fo-pool, software-pipelined over t.
// CTA = (bb, 2-h-row strip); t = 0..30 with 4-slot rolling slice buffer.
// Double-buffered TMEM accumulators + two mbarriers overlap MMA(t+1) with
// epilogue(t). A: two dense ci-planes, LBO=plane/16, SBO=8 (HW-validated).
// B: SW128 blocked atoms (HW-validated). Conflict-free STS.128 fill (R11).
// R12 change: kernel is MUFU(XU)-bound (~98% of 4 ops/SM/cyc). Epilogue
// reassociated to ONE rcp per channel-update:
//   h' = [h(1+b) + a(1-b)] / [(1+a)(1+b)],  a=e^{-gf}, b=e^{-2gz}
// => 2 EX2 + 1 RCP (was 2 EX2 + 2 RCP). Clamps keep denominators finite.
// Also: 32-bit output addressing to cut IMAD chains (alu was 18%).
// ===========================================================================
#define NROWS      2080                       // 4 slots * 520 rows
#define PLANE_B    (NROWS*16)                 // 33280 B per ci-plane
#define SMEM_SLAB  0
#define SMEM_BMAT  (2*PLANE_B)                // 66560, 1024-aligned
#define BMAT_BYTES (28*1024)
#define SMEM_PTR   (SMEM_BMAT + BMAT_BYTES)   // 95232
#define SMEM_MBAR0 (SMEM_PTR + 8)
#define SMEM_MBAR1 (SMEM_PTR + 16)
#define SMEM_BIAS  (SMEM_PTR + 32)
#define SMEM_BYTES (SMEM_BIAS + 128)

#define MMA_IDESC  0x8080010u                 // f16 in, f32 acc, M=128, N=32
#define SWZ128(x) ((x) ^ (((x) >> 3) & 0x70))

__device__ __forceinline__ uint32_t smem_u32(const void* p) {
    uint32_t a;
    asm("{ .reg .u64 t; cvta.to.shared.u64 t, %1; cvt.u32.u64 %0, t; }" : "=r"(a) : "l"(p));
    return a;
}

#if TC_PATH
__device__ __forceinline__ uint32_t elect_one() {
    uint32_t p;
    asm volatile("{\n\t.reg .pred p;\n\telect.sync _|p, 0xFFFFFFFF;\n\t"
                 "selp.b32 %0, 1, 0, p;\n\t}" : "=r"(p));
    return p;
}
__device__ __forceinline__ uint64_t make_desc(uint32_t addr, uint32_t lbo,
                                              uint32_t sbo, uint32_t layout) {
    uint64_t d = 0;
    d |= (uint64_t)(addr >> 4) & 0x3FFF;
    d |= ((uint64_t)lbo & 0x3FFF) << 16;
    d |= ((uint64_t)sbo & 0x3FFF) << 32;
    d |= (uint64_t)1 << 46;
    d |= ((uint64_t)layout & 0x7) << 61;
    return d;
}
__device__ __forceinline__ void mma_f16_ss(uint32_t d_tmem, uint64_t a_desc,
                                           uint64_t b_desc, uint32_t idesc,
                                           uint32_t enable) {
    asm volatile(
        "{\n\t.reg .pred p;\n\tsetp.ne.u32 p, %5, 0;\n\t"
        "tcgen05.mma.cta_group::1.kind::f16 [%0], %1, %2, %3, {%4,%4,%4,%4}, p;\n\t}"
        :: "r"(d_tmem), "l"(a_desc), "l"(b_desc), "r"(idesc), "r"(0u), "r"(enable)
        : "memory");
}
__device__ __forceinline__ void mbar_wait(uint32_t m, uint32_t parity) {
    uint32_t done;
    asm volatile("{\n\t.reg .pred p;\n\t"
        "mbarrier.try_wait.parity.acquire.cta.shared::cta.b64 p, [%1], %2;\n\t"
        "selp.b32 %0, 1, 0, p;\n\t}" : "=r"(done) : "r"(m), "r"(parity) : "memory");
    while (!done)
        asm volatile("{\n\t.reg .pred p;\n\t"
            "mbarrier.try_wait.parity.acquire.cta.shared::cta.b64 p, [%1], %2, 0x989680;\n\t"
            "selp.b32 %0, 1, 0, p;\n\t}" : "=r"(done) : "r"(m), "r"(parity) : "memory");
}

// Issue the 54 MMAs for one time step into D buffer (tmem_d), commit to mbar.
__device__ __forceinline__ void issue_step(int t, uint32_t tmem_d,
                                           uint64_t a_base, uint64_t b_base,
                                           uint32_t mbar) {
    #pragma unroll
    for (int hr = 0; hr < 2; hr++) {
        #pragma unroll
        for (int kc = 0; kc < 27; kc++) {
            const int kd = kc / 9, kh = (kc / 3) % 3, kw = kc % 3;
            const int rowoff = ((t + kd) & 3)*520 + (hr + kh)*130 + kw;
            mma_f16_ss(tmem_d + hr*32,
                       a_base + (uint64_t)rowoff,
                       b_base + (uint64_t)((kc >> 2)*256 + (kc & 3)*2),
                       MMA_IDESC, kc > 0);
        }
    }
    asm volatile(
        "tcgen05.commit.cta_group::1.mbarrier::arrive::one.shared::cluster.b64 [%0];"
        :: "r"(mbar) : "memory");
}
__device__ __forceinline__ float rcp_approx(float x) {
    float r;
    asm("rcp.approx.f32 %0, %1;" : "=f"(r) : "f"(x));
    return r;
}
#endif

// Load one t-slice: thread owns pixels tid and tid+256 of the 512-pixel tile
// (pixel = hh*128 + w). 16 coalesced LDG.32 per pixel, packed to 8 half2.
__device__ __forceinline__ void load_slice(const float* __restrict__ x,
                                           int bb, int hb, int s, int tid,
                                           uint32_t v[16]) {
    #pragma unroll
    for (int pp = 0; pp < 2; pp++) {
        int p  = tid + pp*256;
        int hh = p >> 7;
        int w  = p & 127;
        int gh = hb + hh - 1;
        const bool ok = ((unsigned)s < (unsigned)T_) && ((unsigned)gh < (unsigned)H_);
        const float* xb = x + (size_t)bb*CIN*T_*HW + (size_t)s*HW + (size_t)gh*W_ + w;
        float f[CIN];
        #pragma unroll
        for (int ci = 0; ci < CIN; ci++)
            f[ci] = ok ? xb[(size_t)ci*T_*HW] : 0.f;
        #pragma unroll
        for (int j = 0; j < 8; j++) {
            __half2 h2 = __floats2half2_rn(f[2*j], f[2*j + 1]);
            v[pp*8 + j] = *(uint32_t*)&h2;
        }
    }
}

// Store slice into rolling slot: 4 STS.128, conflict-free.
__device__ __forceinline__ void store_slice(char* smem, int slot, int tid,
                                            const uint32_t v[16]) {
    #pragma unroll
    for (int pp = 0; pp < 2; pp++) {
        int p  = tid + pp*256;
        int hh = p >> 7;
        int w  = p & 127;
        int row = slot*520 + hh*130 + (w + 1);
        #pragma unroll
        for (int pl = 0; pl < 2; pl++) {
            uint4 q = make_uint4(v[pp*8 + pl*4], v[pp*8 + pl*4 + 1],
                                 v[pp*8 + pl*4 + 2], v[pp*8 + pl*4 + 3]);
            *(uint4*)(smem + SMEM_SLAB + pl*PLANE_B + row*16) = q;
        }
    }
}

__global__ __launch_bounds__(256, 2)
void qrnn_fused_kernel(const float* __restrict__ x,
                       const float* __restrict__ Wg,
                       const float* __restrict__ bias,
                       float* __restrict__ out)
{
#if TC_PATH
    extern __shared__ char smem[];
    const uint32_t smem_base = smem_u32(smem);
    float* s_bias = (float*)(smem + SMEM_BIAS);

    const int tid = threadIdx.x;
    const int wid = tid >> 5;
    const int hb  = blockIdx.x * 2;
    const int bb  = blockIdx.y;

    // ---- prologue ----
    if (wid == 0) {
        asm volatile("tcgen05.alloc.cta_group::1.sync.aligned.shared::cta.b32 [%0], %1;"
                     :: "r"(smem_base + SMEM_PTR), "r"(128u) : "memory");
        asm volatile("tcgen05.relinquish_alloc_permit.cta_group::1.sync.aligned;");
    }
    if (tid == 0) {
        asm volatile("mbarrier.init.shared.b64 [%0], %1;"
                     :: "r"(smem_base + SMEM_MBAR0), "r"(1u) : "memory");
        asm volatile("mbarrier.init.shared.b64 [%0], %1;"
                     :: "r"(smem_base + SMEM_MBAR1), "r"(1u) : "memory");
    }
    if (tid < 32) s_bias[tid] = bias[tid];

    // zero the A slab (covers halos, slice -1, and w-edge columns forever)
    for (int i = tid; i < (2*PLANE_B)/16; i += 256)
        *(uint4*)(smem + SMEM_SLAB + i*16) = make_uint4(0,0,0,0);

    // B: [co 32][k 432] K-major SW128 blocked atoms (HW-validated layout)
    for (int idx = tid; idx < 27*16*32; idx += 256) {
        int tap = idx % 27;
        int ci  = (idx / 27) & 15;
        int co  = idx / 432;
        int k   = tap*16 + ci;
        uint32_t byte_off = (uint32_t)(((co >> 3) + (k >> 6)*4)*1024
                                       + (co & 7)*128 + (k & 63)*2);
        *(__half*)(smem + SMEM_BMAT + SWZ128(byte_off)) = __float2half(Wg[idx]);
    }
    __syncthreads();   // slab zero visible before slice stores

    // preload slices 0 and 1 (slice -1 stays zero in slot 0)
    {
        uint32_t v0[16];
        load_slice(x, bb, hb, 0, tid, v0);
        store_slice(smem, 1, tid, v0);
        load_slice(x, bb, hb, 1, tid, v0);
        store_slice(smem, 2, tid, v0);
    }
    asm volatile("fence.proxy.async.shared::cta;" ::: "memory");
    __syncthreads();

    uint32_t tmem_base;
    asm volatile("ld.shared.b32 %0, [%1];" : "=r"(tmem_base) : "r"(smem_base + SMEM_PTR));

    const uint64_t a_base = make_desc(smem_base + SMEM_SLAB, PLANE_B/16, 8, 0);
    const uint64_t b_base = make_desc(smem_base + SMEM_BMAT, 1, 64, 2);
    const bool issuer = (wid == 0) && elect_one();

    // issue step 0 into D0 (slots 0,1,2 ready), then prefetch slice 2
    if (issuer)
        issue_step(0, tmem_base, a_base, b_base, smem_base + SMEM_MBAR0);

    uint32_t v[16];
    load_slice(x, bb, hb, 2, tid, v);

    // epilogue mapping: warpgroup wg owns tile hr = wg, px = w
    const int wg = tid >> 7;
    const int px = tid & 127;
    // 32-bit output offset (out total 65M floats < 4G): base for this thread
    float* const out_base = out + (size_t)((uint32_t)(bb*HID)*(uint32_t)(T_*HW))
                                + (uint32_t)((hb + wg)*W_ + px);
    uint32_t thw = 0;   // t*HW, incremented

    float hstate[HID];
    #pragma unroll
    for (int c = 0; c < HID; c++) hstate[c] = 0.f;
    float bz[HID], bf[HID];
    #pragma unroll
    for (int c = 0; c < HID; c++) { bz[c] = s_bias[c]; bf[c] = s_bias[c + HID]; }

    // ---- pipelined main loop ----
    for (int t = 0; t < T_; t++) {
        // (1) store slice t+2 into slot (t+3)&3 (disjoint from in-flight MMA reads)
        store_slice(smem, (t + 3) & 3, tid, v);
        asm volatile("fence.proxy.async.shared::cta;" ::: "memory");
        __syncthreads();

        // (2) issue NEXT step's MMAs into the other D buffer.
        if (t < T_ - 1 && issuer)
            issue_step(t + 1, tmem_base + ((t + 1) & 1)*64, a_base, b_base,
                       smem_base + (((t + 1) & 1) ? SMEM_MBAR1 : SMEM_MBAR0));

        // (3) prefetch slice t+3
        load_slice(x, bb, hb, t + 3, tid, v);

        // (4) wait for MMA(t), read D[t&1], activation + recurrence + store
        mbar_wait(smem_base + ((t & 1) ? SMEM_MBAR1 : SMEM_MBAR0), (t >> 1) & 1);
        asm volatile("tcgen05.fence::after_thread_sync;" ::: "memory");

        uint32_t d[32];
        asm volatile(
            "tcgen05.ld.sync.aligned.32x32b.x32.b32 "
            "{%0,%1,%2,%3,%4,%5,%6,%7,%8,%9,%10,%11,%12,%13,%14,%15,"
            "%16,%17,%18,%19,%20,%21,%22,%23,%24,%25,%26,%27,%28,%29,%30,%31}, [%32];"
            : "=r"(d[0]),"=r"(d[1]),"=r"(d[2]),"=r"(d[3]),"=r"(d[4]),"=r"(d[5]),
              "=r"(d[6]),"=r"(d[7]),"=r"(d[8]),"=r"(d[9]),"=r"(d[10]),"=r"(d[11]),
              "=r"(d[12]),"=r"(d[13]),"=r"(d[14]),"=r"(d[15]),"=r"(d[16]),"=r"(d[17]),
              "=r"(d[18]),"=r"(d[19]),"=r"(d[20]),"=r"(d[21]),"=r"(d[22]),"=r"(d[23]),
              "=r"(d[24]),"=r"(d[25]),"=r"(d[26]),"=r"(d[27]),"=r"(d[28]),"=r"(d[29]),
              "=r"(d[30]),"=r"(d[31])
            : "r"(tmem_base + (t & 1)*64 + wg*32));
        asm volatile("tcgen05.wait::ld.sync.aligned;" ::: "memory");

        // 3-MUFU fo-pool update (exact reassociation):
        //   a = e^{-gf}, b = e^{-2gz}
        //   h' = (h*(1+b) + a*(1-b)) / ((1+a)*(1+b))
        #pragma unroll
        for (int c = 0; c < HID; c++) {
            float gz = __uint_as_float(d[c])       + bz[c];
            float gf = __uint_as_float(d[c + HID]) + bf[c];
            gz = fmaxf(gz, -12.f);     // tanh saturated; keeps b <= e^24
            gf = fmaxf(gf, -25.f);     // sigmoid saturated; keeps a <= e^25
            float b = exp2f(gz * -2.885390082f);   // e^{-2gz}  (FMUL+EX2)
            float a = exp2f(gf * -1.442695041f);   // e^{-gf}   (FMUL+EX2)
            float r = rcp_approx((1.f + a) * (1.f + b));
            float num = fmaf(hstate[c], b, hstate[c]) + a * (1.f - b);
            hstate[c] = num * r;
            out_base[(uint32_t)(c*(T_*HW)) + thw] = hstate[c];
        }
        thw += HW;

        // (5) order this step's TMEM reads before MMA(t+2) rewrites D[t&1].
        asm volatile("tcgen05.fence::before_thread_sync;" ::: "memory");
    }

    __syncthreads();
    if (wid == 0)
        asm volatile("tcgen05.dealloc.cta_group::1.sync.aligned.b32 %0, %1;"
                     :: "r"(tmem_base), "r"(128u));
#endif  // TC_PATH
}

extern "C" void kernel_launch(void* const* d_in, const int* in_sizes, int n_in,
                              void* d_out, int out_size)
{
    (void)in_sizes; (void)n_in; (void)out_size;
    const float* x    = (const float*)d_in[0];
    const float* Wg   = (const float*)d_in[1];
    const float* bias = (const float*)d_in[2];
    float* out = (float*)d_out;

    cudaFuncSetAttribute(qrnn_fused_kernel,
                         cudaFuncAttributeMaxDynamicSharedMemorySize, SMEM_BYTES);

    dim3 grid(H_ / 2, B_);   // 64 x 4 = 256 CTAs, 2/SM resident -> 1 wave
    qrnn_fused_kernel<<<grid, 256, SMEM_BYTES>>>(x, Wg, bias, out);
}

// round 13
// speedup vs baseline: 1.0738x; 1.0738x over previous
#include <cuda_runtime.h>
#include <cuda_fp16.h>
#include <math.h>
#include <stdint.h>

// Problem constants
#define B_    4
#define CIN   16
#define T_    31
#define H_    128
#define W_    128
#define HID   16
#define HW    (H_*W_)

// Arch-specific feature gate: tcgen05 PTX only assembles for sm_103a/f targets.
#if (defined(__CUDA_ARCH_SPECIFIC__) && (__CUDA_ARCH_SPECIFIC__ >= 1000)) || \
    (defined(__CUDA_ARCH_FAMILY_SPECIFIC__) && (__CUDA_ARCH_FAMILY_SPECIFIC__ >= 1000))
#define TC_PATH 1
#else
#define TC_PATH 0
#endif

// ===========================================================================
// Persistent fused conv + fo-pool, software-pipelined over t (R11 baseline,
// 121.6us). R13 change: epilogue candidate gate uses HW tanh.approx.f32
// (1 MUFU, abs err ~4.9e-4 damped by (1-f) and the contractive recurrence);
// sigmoid stays exact-path (its error is amplified by (h-z)). Cuts epilogue
// from ~14 to ~10 instrs/channel — the kernel is issue-bound on the epilogue.
// ===========================================================================
#define NROWS      2080                       // 4 slots * 520 rows
#define PLANE_B    (NROWS*16)                 // 33280 B per ci-plane
#define SMEM_SLAB  0
#define SMEM_BMAT  (2*PLANE_B)                // 66560, 1024-aligned
#define BMAT_BYTES (28*1024)
#define SMEM_PTR   (SMEM_BMAT + BMAT_BYTES)   // 95232
#define SMEM_MBAR0 (SMEM_PTR + 8)
#define SMEM_MBAR1 (SMEM_PTR + 16)
#define SMEM_BIAS  (SMEM_PTR + 32)
#define SMEM_BYTES (SMEM_BIAS + 128)

#define MMA_IDESC  0x8080010u                 // f16 in, f32 acc, M=128, N=32
#define SWZ128(x) ((x) ^ (((x) >> 3) & 0x70))

__device__ __forceinline__ uint32_t smem_u32(const void* p) {
    uint32_t a;
    asm("{ .reg .u64 t; cvta.to.shared.u64 t, %1; cvt.u32.u64 %0, t; }" : "=r"(a) : "l"(p));
    return a;
}

#if TC_PATH
__device__ __forceinline__ uint32_t elect_one() {
    uint32_t p;
    asm volatile("{\n\t.reg .pred p;\n\telect.sync _|p, 0xFFFFFFFF;\n\t"
                 "selp.b32 %0, 1, 0, p;\n\t}" : "=r"(p));
    return p;
}
__device__ __forceinline__ uint64_t make_desc(uint32_t addr, uint32_t lbo,
                                              uint32_t sbo, uint32_t layout) {
    uint64_t d = 0;
    d |= (uint64_t)(addr >> 4) & 0x3FFF;
    d |= ((uint64_t)lbo & 0x3FFF) << 16;
    d |= ((uint64_t)sbo & 0x3FFF) << 32;
    d |= (uint64_t)1 << 46;
    d |= ((uint64_t)layout & 0x7) << 61;
    return d;
}
__device__ __forceinline__ void mma_f16_ss(uint32_t d_tmem, uint64_t a_desc,
                                           uint64_t b_desc, uint32_t idesc,
                                           uint32_t enable) {
    asm volatile(
        "{\n\t.reg .pred p;\n\tsetp.ne.u32 p, %5, 0;\n\t"
        "tcgen05.mma.cta_group::1.kind::f16 [%0], %1, %2, %3, {%4,%4,%4,%4}, p;\n\t}"
        :: "r"(d_tmem), "l"(a_desc), "l"(b_desc), "r"(idesc), "r"(0u), "r"(enable)
        : "memory");
}
__device__ __forceinline__ void mbar_wait(uint32_t m, uint32_t parity) {
    uint32_t done;
    asm volatile("{\n\t.reg .pred p;\n\t"
        "mbarrier.try_wait.parity.acquire.cta.shared::cta.b64 p, [%1], %2;\n\t"
        "selp.b32 %0, 1, 0, p;\n\t}" : "=r"(done) : "r"(m), "r"(parity) : "memory");
    while (!done)
        asm volatile("{\n\t.reg .pred p;\n\t"
            "mbarrier.try_wait.parity.acquire.cta.shared::cta.b64 p, [%1], %2, 0x989680;\n\t"
            "selp.b32 %0, 1, 0, p;\n\t}" : "=r"(done) : "r"(m), "r"(parity) : "memory");
}

// Issue the 54 MMAs for one time step into D buffer (tmem_d), commit to mbar.
__device__ __forceinline__ void issue_step(int t, uint32_t tmem_d,
                                           uint64_t a_base, uint64_t b_base,
                                           uint32_t mbar) {
    #pragma unroll
    for (int hr = 0; hr < 2; hr++) {
        #pragma unroll
        for (int kc = 0; kc < 27; kc++) {
            const int kd = kc / 9, kh = (kc / 3) % 3, kw = kc % 3;
            const int rowoff = ((t + kd) & 3)*520 + (hr + kh)*130 + kw;
            mma_f16_ss(tmem_d + hr*32,
                       a_base + (uint64_t)rowoff,
                       b_base + (uint64_t)((kc >> 2)*256 + (kc & 3)*2),
                       MMA_IDESC, kc > 0);
        }
    }
    asm volatile(
        "tcgen05.commit.cta_group::1.mbarrier::arrive::one.shared::cluster.b64 [%0];"
        :: "r"(mbar) : "memory");
}
__device__ __forceinline__ float rcp_approx(float x) {
    float r;
    asm("rcp.approx.f32 %0, %1;" : "=f"(r) : "f"(x));
    return r;
}
__device__ __forceinline__ float tanh_approx(float x) {
    float r;
    asm("tanh.approx.f32 %0, %1;" : "=f"(r) : "f"(x));
    return r;
}
#endif

// Load one t-slice: thread owns pixels tid and tid+256 of the 512-pixel tile
// (pixel = hh*128 + w). 16 coalesced LDG.32 per pixel, packed to 8 half2.
__device__ __forceinline__ void load_slice(const float* __restrict__ x,
                                           int bb, int hb, int s, int tid,
                                           uint32_t v[16]) {
    #pragma unroll
    for (int pp = 0; pp < 2; pp++) {
        int p  = tid + pp*256;
        int hh = p >> 7;
        int w  = p & 127;
        int gh = hb + hh - 1;
        const bool ok = ((unsigned)s < (unsigned)T_) && ((unsigned)gh < (unsigned)H_);
        const float* xb = x + (size_t)bb*CIN*T_*HW + (size_t)s*HW + (size_t)gh*W_ + w;
        float f[CIN];
        #pragma unroll
        for (int ci = 0; ci < CIN; ci++)
            f[ci] = ok ? xb[(size_t)ci*T_*HW] : 0.f;
        #pragma unroll
        for (int j = 0; j < 8; j++) {
            __half2 h2 = __floats2half2_rn(f[2*j], f[2*j + 1]);
            v[pp*8 + j] = *(uint32_t*)&h2;
        }
    }
}

// Store slice into rolling slot: 4 STS.128, conflict-free.
__device__ __forceinline__ void store_slice(char* smem, int slot, int tid,
                                            const uint32_t v[16]) {
    #pragma unroll
    for (int pp = 0; pp < 2; pp++) {
        int p  = tid + pp*256;
        int hh = p >> 7;
        int w  = p & 127;
        int row = slot*520 + hh*130 + (w + 1);
        #pragma unroll
        for (int pl = 0; pl < 2; pl++) {
            uint4 q = make_uint4(v[pp*8 + pl*4], v[pp*8 + pl*4 + 1],
                                 v[pp*8 + pl*4 + 2], v[pp*8 + pl*4 + 3]);
            *(uint4*)(smem + SMEM_SLAB + pl*PLANE_B + row*16) = q;
        }
    }
}

__global__ __launch_bounds__(256, 2)
void qrnn_fused_kernel(const float* __restrict__ x,
                       const float* __restrict__ Wg,
                       const float* __restrict__ bias,
                       float* __restrict__ out)
{
#if TC_PATH
    extern __shared__ char smem[];
    const uint32_t smem_base = smem_u32(smem);
    float* s_bias = (float*)(smem + SMEM_BIAS);

    const int tid = threadIdx.x;
    const int wid = tid >> 5;
    const int hb  = blockIdx.x * 2;
    const int bb  = blockIdx.y;

    // ---- prologue ----
    if (wid == 0) {
        asm volatile("tcgen05.alloc.cta_group::1.sync.aligned.shared::cta.b32 [%0], %1;"
                     :: "r"(smem_base + SMEM_PTR), "r"(128u) : "memory");
        asm volatile("tcgen05.relinquish_alloc_permit.cta_group::1.sync.aligned;");
    }
    if (tid == 0) {
        asm volatile("mbarrier.init.shared.b64 [%0], %1;"
                     :: "r"(smem_base + SMEM_MBAR0), "r"(1u) : "memory");
        asm volatile("mbarrier.init.shared.b64 [%0], %1;"
                     :: "r"(smem_base + SMEM_MBAR1), "r"(1u) : "memory");
    }
    if (tid < 32) s_bias[tid] = bias[tid];

    // zero the A slab (covers halos, slice -1, and w-edge columns forever)
    for (int i = tid; i < (2*PLANE_B)/16; i += 256)
        *(uint4*)(smem + SMEM_SLAB + i*16) = make_uint4(0,0,0,0);

    // B: [co 32][k 432] K-major SW128 blocked atoms (HW-validated layout)
    for (int idx = tid; idx < 27*16*32; idx += 256) {
        int tap = idx % 27;
        int ci  = (idx / 27) & 15;
        int co  = idx / 432;
        int k   = tap*16 + ci;
        uint32_t byte_off = (uint32_t)(((co >> 3) + (k >> 6)*4)*1024
                                       + (co & 7)*128 + (k & 63)*2);
        *(__half*)(smem + SMEM_BMAT + SWZ128(byte_off)) = __float2half(Wg[idx]);
    }
    __syncthreads();   // slab zero visible before slice stores

    // preload slices 0 and 1 (slice -1 stays zero in slot 0)
    {
        uint32_t v0[16];
        load_slice(x, bb, hb, 0, tid, v0);
        store_slice(smem, 1, tid, v0);
        load_slice(x, bb, hb, 1, tid, v0);
        store_slice(smem, 2, tid, v0);
    }
    asm volatile("fence.proxy.async.shared::cta;" ::: "memory");
    __syncthreads();

    uint32_t tmem_base;
    asm volatile("ld.shared.b32 %0, [%1];" : "=r"(tmem_base) : "r"(smem_base + SMEM_PTR));

    const uint64_t a_base = make_desc(smem_base + SMEM_SLAB, PLANE_B/16, 8, 0);
    const uint64_t b_base = make_desc(smem_base + SMEM_BMAT, 1, 64, 2);
    const bool issuer = (wid == 0) && elect_one();

    // issue step 0 into D0 (slots 0,1,2 ready), then prefetch slice 2
    if (issuer)
        issue_step(0, tmem_base, a_base, b_base, smem_base + SMEM_MBAR0);

    uint32_t v[16];
    load_slice(x, bb, hb, 2, tid, v);

    // epilogue mapping: warpgroup wg owns tile hr = wg, px = w
    const int wg = tid >> 7;
    const int px = tid & 127;
    const size_t out_rowbase = (size_t)(hb + wg)*W_ + px;

    float hstate[HID];
    #pragma unroll
    for (int c = 0; c < HID; c++) hstate[c] = 0.f;
    float bz[HID], bf[HID];
    #pragma unroll
    for (int c = 0; c < HID; c++) { bz[c] = s_bias[c]; bf[c] = s_bias[c + HID]; }

    // ---- pipelined main loop ----
    for (int t = 0; t < T_; t++) {
        // (1) store slice t+2 into slot (t+3)&3 (disjoint from in-flight MMA reads)
        store_slice(smem, (t + 3) & 3, tid, v);
        asm volatile("fence.proxy.async.shared::cta;" ::: "memory");
        __syncthreads();

        // (2) issue NEXT step's MMAs into the other D buffer.
        if (t < T_ - 1 && issuer)
            issue_step(t + 1, tmem_base + ((t + 1) & 1)*64, a_base, b_base,
                       smem_base + (((t + 1) & 1) ? SMEM_MBAR1 : SMEM_MBAR0));

        // (3) prefetch slice t+3
        load_slice(x, bb, hb, t + 3, tid, v);

        // (4) wait for MMA(t), read D[t&1], activation + recurrence + store
        mbar_wait(smem_base + ((t & 1) ? SMEM_MBAR1 : SMEM_MBAR0), (t >> 1) & 1);
        asm volatile("tcgen05.fence::after_thread_sync;" ::: "memory");

        uint32_t d[32];
        asm volatile(
            "tcgen05.ld.sync.aligned.32x32b.x32.b32 "
            "{%0,%1,%2,%3,%4,%5,%6,%7,%8,%9,%10,%11,%12,%13,%14,%15,"
            "%16,%17,%18,%19,%20,%21,%22,%23,%24,%25,%26,%27,%28,%29,%30,%31}, [%32];"
            : "=r"(d[0]),"=r"(d[1]),"=r"(d[2]),"=r"(d[3]),"=r"(d[4]),"=r"(d[5]),
              "=r"(d[6]),"=r"(d[7]),"=r"(d[8]),"=r"(d[9]),"=r"(d[10]),"=r"(d[11]),
              "=r"(d[12]),"=r"(d[13]),"=r"(d[14]),"=r"(d[15]),"=r"(d[16]),"=r"(d[17]),
              "=r"(d[18]),"=r"(d[19]),"=r"(d[20]),"=r"(d[21]),"=r"(d[22]),"=r"(d[23]),
              "=r"(d[24]),"=r"(d[25]),"=r"(d[26]),"=r"(d[27]),"=r"(d[28]),"=r"(d[29]),
              "=r"(d[30]),"=r"(d[31])
            : "r"(tmem_base + (t & 1)*64 + wg*32));
        asm volatile("tcgen05.wait::ld.sync.aligned;" ::: "memory");

        // Lean epilogue: z = tanh.approx (1 MUFU, err damped by (1-f) and the
        // contractive recurrence); f = exact sigmoid via EX2+RCP (its error is
        // amplified by (h-z), so no approximation there).
        #pragma unroll
        for (int c = 0; c < HID; c++) {
            float gz = __uint_as_float(d[c])       + bz[c];
            float gf = __uint_as_float(d[c + HID]) + bf[c];
            float z  = tanh_approx(gz);
            float e  = exp2f(gf * -1.442695041f);          // e^{-gf}
            float f  = rcp_approx(1.f + e);                // sigmoid
            hstate[c] = f * (hstate[c] - z) + z;
            out[((size_t)(bb*HID + c)*T_ + t)*HW + out_rowbase] = hstate[c];
        }

        // (5) order this step's TMEM reads before MMA(t+2) rewrites D[t&1].
        asm volatile("tcgen05.fence::before_thread_sync;" ::: "memory");
    }

    __syncthreads();
    if (wid == 0)
        asm volatile("tcgen05.dealloc.cta_group::1.sync.aligned.b32 %0, %1;"
                     :: "r"(tmem_base), "r"(128u));
#endif  // TC_PATH
}

extern "C" void kernel_launch(void* const* d_in, const int* in_sizes, int n_in,
                              void* d_out, int out_size)
{
    (void)in_sizes; (void)n_in; (void)out_size;
    const float* x    = (const float*)d_in[0];
    const float* Wg   = (const float*)d_in[1];
    const float* bias = (const float*)d_in[2];
    float* out = (float*)d_out;

    cudaFuncSetAttribute(qrnn_fused_kernel,
                         cudaFuncAttributeMaxDynamicSharedMemorySize, SMEM_BYTES);

    dim3 grid(H_ / 2, B_);   // 64 x 4 = 256 CTAs, 2/SM resident -> 1 wave
    qrnn_fused_kernel<<<grid, 256, SMEM_BYTES>>>(x, Wg, bias, out);
}